// round 3
// baseline (speedup 1.0000x reference)
#include <cuda_runtime.h>
#include <cstdint>

// Sizes
#define BSZ 512
#define HID 1024
#define NG  4096
#define INP 128
#define SEQ 96

// Scratch (__device__ globals; no cudaMalloc allowed)
__device__ float d_Weff[(size_t)NG * HID];   // permuted rows, tf32-rounded
__device__ float d_beff[NG];                 // permuted
__device__ float d_D0[(size_t)BSZ * NG];     // step-0 correction, permuted
__device__ float d_u0[BSZ * INP];
__device__ float d_hbuf[2][(size_t)BSZ * HID];
__device__ float d_cbuf[(size_t)BSZ * HID];
__device__ float d_part[(size_t)SEQ * 32 * BSZ];  // [t][ntile][b]

__device__ __forceinline__ float to_tf32(float x) {
    unsigned r; asm("cvt.rna.tf32.f32 %0, %1;" : "=r"(r) : "f"(x));
    return __uint_as_float(r);
}
__device__ __forceinline__ float sigm(float x) { return 1.0f / (1.0f + __expf(-x)); }
// permuted gate row n' = 4j+g  ->  original row r = g*1024 + j
__device__ __forceinline__ int permrow(int np) { return ((np & 3) << 10) | (np >> 2); }

__device__ __forceinline__ void cpa16(uint32_t s, const void* g) {
    asm volatile("cp.async.cg.shared.global [%0], [%1], 16;\n" :: "r"(s), "l"(g));
}
__device__ __forceinline__ void mma8(float* c, const unsigned* a, const unsigned* b) {
    asm volatile(
        "mma.sync.aligned.m16n8k8.row.col.f32.tf32.tf32.f32 "
        "{%0,%1,%2,%3}, {%4,%5,%6,%7}, {%8,%9}, {%0,%1,%2,%3};"
        : "+f"(c[0]), "+f"(c[1]), "+f"(c[2]), "+f"(c[3])
        : "r"(a[0]), "r"(a[1]), "r"(a[2]), "r"(a[3]), "r"(b[0]), "r"(b[1]));
}

// ---------------- Precompute kernels ----------------

// W_eff[n'][m] = W_hh[r][m] + sum_k W_ih[r][k]*W_fc[k][m]  (4 rows per block-row)
__global__ void k_weff(const float* __restrict__ Wih, const float* __restrict__ Whh,
                       const float* __restrict__ Wfc) {
    int m = blockIdx.x * 256 + threadIdx.x;   // grid.x = 4
    int npb = blockIdx.y * 4;                 // grid.y = 1024
    float acc[4]; int r[4];
    #pragma unroll
    for (int i = 0; i < 4; i++) {
        r[i] = permrow(npb + i);
        acc[i] = Whh[(size_t)r[i] * HID + m];
    }
    for (int k = 0; k < INP; k++) {
        float w = Wfc[k * HID + m];
        #pragma unroll
        for (int i = 0; i < 4; i++) acc[i] += Wih[r[i] * INP + k] * w;
    }
    #pragma unroll
    for (int i = 0; i < 4; i++) d_Weff[(size_t)(npb + i) * HID + m] = to_tf32(acc[i]);
}

// h0 (tf32-rounded) and c0 init
__global__ void k_state(const float* __restrict__ hid, const float* __restrict__ cell) {
    int i = blockIdx.x * 256 + threadIdx.x;   // grid 2048
    d_hbuf[0][i] = to_tf32(hid[i]);
    d_cbuf[i] = cell[i];
}

// u0[b][k] = x0[b][k] - b_fc[k] - h0[b]·W_fc[k]
__global__ void k_u0(const float* __restrict__ xt, const float* __restrict__ hid,
                     const float* __restrict__ Wfc, const float* __restrict__ bfc) {
    __shared__ float hs[HID];
    int b = blockIdx.x, k = threadIdx.x;      // 512 blocks x 128 threads
    for (int i = k; i < HID; i += 128) hs[i] = hid[b * HID + i];
    __syncthreads();
    float acc = 0.f;
    const float* w = Wfc + k * HID;
    for (int i = 0; i < HID; i++) acc += hs[i] * w[i];
    d_u0[b * INP + k] = xt[b * INP + k] - bfc[k] - acc;
}

// b_eff[n'] = b_ih[r]+b_hh[r]+W_ih[r]·b_fc
__global__ void k_beff(const float* __restrict__ Wih, const float* __restrict__ bih,
                       const float* __restrict__ bhh, const float* __restrict__ bfc) {
    int np = blockIdx.x * 256 + threadIdx.x;  // grid 16
    int r = permrow(np);
    float acc = bih[r] + bhh[r];
    for (int k = 0; k < INP; k++) acc += Wih[r * INP + k] * bfc[k];
    d_beff[np] = acc;
}

// D0[b][n'] = u0[b]·W_ih[r]   (4 b's per block)
__global__ void k_d0(const float* __restrict__ Wih) {
    __shared__ float us[4][INP];
    int tid = threadIdx.x;                    // 128
    int bq = blockIdx.y;                      // 0..127
    int np = blockIdx.x * 128 + tid;          // grid.x 32
    #pragma unroll
    for (int i = 0; i < 4; i++) us[i][tid] = d_u0[(bq * 4 + i) * INP + tid];
    __syncthreads();
    int r = permrow(np);
    float a0 = 0, a1 = 0, a2 = 0, a3 = 0;
    for (int k = 0; k < INP; k++) {
        float w = Wih[r * INP + k];
        a0 += us[0][k] * w; a1 += us[1][k] * w; a2 += us[2][k] * w; a3 += us[3][k] * w;
    }
    d_D0[(size_t)(bq * 4 + 0) * NG + np] = a0;
    d_D0[(size_t)(bq * 4 + 1) * NG + np] = a1;
    d_D0[(size_t)(bq * 4 + 2) * NG + np] = a2;
    d_D0[(size_t)(bq * 4 + 3) * NG + np] = a3;
}

// ---------------- Step kernel: gates GEMM + fused LSTM epilogue ----------------
// CTA tile 128x128, K=1024 in 32-wide chunks, 3-stage cp.async pipeline.
// smem per stage: A[128][36] + B[128][36] floats = 9216 floats; 3 stages = 110592 B.
#define KSTRIDE 36
#define STAGEF  (2 * 128 * KSTRIDE)
#define SMEM_BYTES (3 * STAGEF * 4)

__global__ void __launch_bounds__(256, 1)
k_step(int t, int par, const float* __restrict__ Wfc) {
    extern __shared__ float sm[];
    const int tid = threadIdx.x, lane = tid & 31, wid = tid >> 5;
    const int wm = wid & 1, wn = wid >> 1;          // 2 x 4 warp grid (64M x 32N each)
    const int ntile = blockIdx.x, mtile = blockIdx.y;
    const int m0 = mtile * 128, n0 = ntile * 128;
    const float* hp = d_hbuf[par];
    float* hnx = d_hbuf[par ^ 1];
    const int gid = lane >> 2, tig = lane & 3;

    float acc[4][4][4];
    #pragma unroll
    for (int a = 0; a < 4; a++)
        #pragma unroll
        for (int b = 0; b < 4; b++)
            #pragma unroll
            for (int c = 0; c < 4; c++) acc[a][b][c] = 0.f;

    auto issue = [&](int kc, int s) {
        const float* Ag = hp + (size_t)m0 * HID + kc * 32;
        const float* Bg = d_Weff + (size_t)n0 * HID + kc * 32;
        float* As = sm + s * STAGEF;
        float* Bs = As + 128 * KSTRIDE;
        #pragma unroll
        for (int p = 0; p < 4; p++) {
            int id = tid + p * 256;
            int row = id >> 3, c4 = (id & 7) * 4;
            cpa16((uint32_t)__cvta_generic_to_shared(&As[row * KSTRIDE + c4]),
                  Ag + row * HID + c4);
            cpa16((uint32_t)__cvta_generic_to_shared(&Bs[row * KSTRIDE + c4]),
                  Bg + row * HID + c4);
        }
        asm volatile("cp.async.commit_group;\n");
    };

    auto compute = [&](int s) {
        const unsigned* As = (const unsigned*)(sm + s * STAGEF);
        const unsigned* Bs = As + 128 * KSTRIDE;
        #pragma unroll
        for (int k8 = 0; k8 < 32; k8 += 8) {
            unsigned a[4][4], b[4][2];
            #pragma unroll
            for (int mf = 0; mf < 4; mf++) {
                int r = wm * 64 + mf * 16 + gid;
                a[mf][0] = As[r * KSTRIDE + k8 + tig];
                a[mf][1] = As[(r + 8) * KSTRIDE + k8 + tig];
                a[mf][2] = As[r * KSTRIDE + k8 + tig + 4];
                a[mf][3] = As[(r + 8) * KSTRIDE + k8 + tig + 4];
            }
            #pragma unroll
            for (int nf = 0; nf < 4; nf++) {
                int n = wn * 32 + nf * 8 + gid;
                b[nf][0] = Bs[n * KSTRIDE + k8 + tig];
                b[nf][1] = Bs[n * KSTRIDE + k8 + tig + 4];
            }
            #pragma unroll
            for (int mf = 0; mf < 4; mf++)
                #pragma unroll
                for (int nf = 0; nf < 4; nf++) mma8(acc[mf][nf], a[mf], b[nf]);
        }
    };

    issue(0, 0);
    issue(1, 1);
    for (int kc = 0; kc < 32; kc++) {
        asm volatile("cp.async.wait_group 1;\n" ::: "memory");
        __syncthreads();
        if (kc + 2 < 32) issue(kc + 2, (kc + 2) % 3);
        else asm volatile("cp.async.commit_group;\n");
        compute(kc % 3);
    }
    asm volatile("cp.async.wait_group 0;\n" ::: "memory");
    __syncthreads();

    // dump C tile to smem (stride 132)
    #pragma unroll
    for (int mf = 0; mf < 4; mf++)
        #pragma unroll
        for (int nf = 0; nf < 4; nf++) {
            int row = wm * 64 + mf * 16 + gid;
            int col = wn * 32 + nf * 8 + 2 * tig;
            sm[row * 132 + col]           = acc[mf][nf][0];
            sm[row * 132 + col + 1]       = acc[mf][nf][1];
            sm[(row + 8) * 132 + col]     = acc[mf][nf][2];
            sm[(row + 8) * 132 + col + 1] = acc[mf][nf][3];
        }
    __syncthreads();

    // fused LSTM epilogue: thread = (bl, half of 32 units)
    int bl = tid >> 1, jh = tid & 1;
    int b = m0 + bl;
    float partial = 0.f;
    #pragma unroll
    for (int jj = 0; jj < 16; jj++) {
        int jl = jh * 16 + jj;
        int nl = 4 * jl;
        int jg = ntile * 32 + jl;
        float gi = sm[bl * 132 + nl]     + d_beff[n0 + nl];
        float gf = sm[bl * 132 + nl + 1] + d_beff[n0 + nl + 1];
        float gg = sm[bl * 132 + nl + 2] + d_beff[n0 + nl + 2];
        float go = sm[bl * 132 + nl + 3] + d_beff[n0 + nl + 3];
        if (t == 0) {
            const float* dd = d_D0 + (size_t)b * NG + n0 + nl;
            gi += dd[0]; gf += dd[1]; gg += dd[2]; go += dd[3];
        }
        float c_old = d_cbuf[b * HID + jg];
        float cn = sigm(gf) * c_old + sigm(gi) * tanhf(gg);
        float hv = sigm(go) * tanhf(cn);
        d_cbuf[b * HID + jg] = cn;
        hnx[b * HID + jg] = to_tf32(hv);
        partial += hv * Wfc[127 * HID + jg];
    }
    partial += __shfl_xor_sync(0xffffffffu, partial, 1);
    if (jh == 0) d_part[(size_t)t * (32 * BSZ) + ntile * BSZ + b] = partial;
}

// out[b][t] = b_fc[127] + sum over 32 tiles
__global__ void k_reduce(float* __restrict__ out, const float* __restrict__ bfc) {
    int idx = blockIdx.x * 256 + threadIdx.x;
    if (idx >= BSZ * SEQ) return;
    int b = idx / SEQ, t = idx % SEQ;
    float s = bfc[127];
    #pragma unroll 8
    for (int nt = 0; nt < 32; nt++) s += d_part[(size_t)t * (32 * BSZ) + nt * BSZ + b];
    out[idx] = s;
}

extern "C" void kernel_launch(void* const* d_in, const int* in_sizes, int n_in,
                              void* d_out, int out_size) {
    const float* xt   = (const float*)d_in[0];
    const float* hid  = (const float*)d_in[1];
    const float* cell = (const float*)d_in[2];
    const float* Wih  = (const float*)d_in[3];
    const float* Whh  = (const float*)d_in[4];
    const float* bih  = (const float*)d_in[5];
    const float* bhh  = (const float*)d_in[6];
    const float* Wfc  = (const float*)d_in[7];
    const float* bfc  = (const float*)d_in[8];
    float* out = (float*)d_out;

    cudaFuncSetAttribute(k_step, cudaFuncAttributeMaxDynamicSharedMemorySize, SMEM_BYTES);

    k_weff<<<dim3(4, 1024), 256>>>(Wih, Whh, Wfc);
    k_state<<<2048, 256>>>(hid, cell);
    k_u0<<<512, 128>>>(xt, hid, Wfc, bfc);
    k_beff<<<16, 256>>>(Wih, bih, bhh, bfc);
    k_d0<<<dim3(32, 128), 128>>>(Wih);
    for (int t = 0; t < SEQ; t++)
        k_step<<<dim3(32, 4), 256, SMEM_BYTES>>>(t, t & 1, Wfc);
    k_reduce<<<192, 256>>>(out, bfc);
}

// round 5
// speedup vs baseline: 1.3310x; 1.3310x over previous
#include <cuda_runtime.h>
#include <cstdint>

// Sizes
#define BSZ 512
#define HID 1024
#define NG  4096
#define INP 128
#define SEQ 96
#define NCH 32            // K chunks of 32 floats
#define TILEF 4096        // floats per 128x32 tile
#define TILEB 16384       // bytes per tile
#define STG 4             // pipeline stages
#define SMEM_BYTES (STG * 2 * TILEB)   // 131072 dynamic

// Scratch (__device__ globals; no cudaMalloc allowed)
__device__ __align__(128) float d_Weff[(size_t)NG * HID];   // tiled+swizzled [ntile*32+ch][128][32]
__device__ float d_beff[NG];                                // permuted linear
__device__ float d_D0[(size_t)BSZ * NG];                    // step-0 correction [b][n']
__device__ float d_u0[BSZ * INP];
__device__ __align__(128) float d_hbuf[2][(size_t)BSZ * HID]; // tiled+swizzled [mtile*32+ch][128][32]
__device__ float d_cbuf[(size_t)BSZ * HID];                  // linear [b][j]
__device__ float d_part[(size_t)SEQ * 32 * BSZ];

__device__ __forceinline__ float to_tf32(float x) {
    unsigned r; asm("cvt.rna.tf32.f32 %0, %1;" : "=r"(r) : "f"(x));
    return __uint_as_float(r);
}
__device__ __forceinline__ float sigm(float x) { return 1.0f / (1.0f + __expf(-x)); }
__device__ __forceinline__ int permrow(int np) { return ((np & 3) << 10) | (np >> 2); }
// byte-offset SW128-style swizzle for 128B rows
__device__ __forceinline__ uint32_t sw128(uint32_t o) { return o ^ ((o >> 3) & 0x70); }

__device__ __forceinline__ uint32_t s2u(const void* p) {
    uint32_t a;
    asm("{ .reg .u64 t; cvta.to.shared.u64 t, %1; cvt.u32.u64 %0, t; }" : "=r"(a) : "l"(p));
    return a;
}
__device__ __forceinline__ void bulkcp(uint32_t dst, const void* src, uint32_t bytes, uint32_t mbar) {
    asm volatile(
        "cp.async.bulk.shared::cluster.global.mbarrier::complete_tx::bytes [%0], [%1], %2, [%3];"
        :: "r"(dst), "l"(src), "r"(bytes), "r"(mbar) : "memory");
}
__device__ __forceinline__ void mma8(float* c, const unsigned* a, const unsigned* b) {
    asm volatile(
        "mma.sync.aligned.m16n8k8.row.col.f32.tf32.tf32.f32 "
        "{%0,%1,%2,%3}, {%4,%5,%6,%7}, {%8,%9}, {%0,%1,%2,%3};"
        : "+f"(c[0]), "+f"(c[1]), "+f"(c[2]), "+f"(c[3])
        : "r"(a[0]), "r"(a[1]), "r"(a[2]), "r"(a[3]), "r"(b[0]), "r"(b[1]));
}
#define MBINIT(a, n) \
    asm volatile("mbarrier.init.shared.b64 [%0], %1;" :: "r"(a), "r"(n) : "memory")
#define MBEXPECT(a, n) \
    asm volatile("mbarrier.arrive.expect_tx.shared.b64 _, [%0], %1;" :: "r"(a), "r"(n) : "memory")
#define MBWAIT(a, ph) \
    asm volatile("{\n\t.reg .pred P;\n\tWL_%=: mbarrier.try_wait.parity.acquire.cta.shared::cta.b64 P, [%0], %1, 0x989680;\n\t@P bra.uni WD_%=;\n\tbra.uni WL_%=;\n\tWD_%=:\n\t}" \
                 :: "r"(a), "r"((uint32_t)(ph)) : "memory")
#define FPROXY() asm volatile("fence.proxy.async.shared::cta;" ::: "memory")

// ---------------- Precompute kernels ----------------

// W_eff[n'][m] = W_hh[r][m] + sum_k W_ih[r][k]*W_fc[k][m]; tiled+swizzled tf32 store
__global__ void k_weff(const float* __restrict__ Wih, const float* __restrict__ Whh,
                       const float* __restrict__ Wfc) {
    int m = blockIdx.x * 256 + threadIdx.x;   // grid.x = 4
    int npb = blockIdx.y * 4;                 // grid.y = 1024
    float acc[4]; int r[4];
    #pragma unroll
    for (int i = 0; i < 4; i++) {
        r[i] = permrow(npb + i);
        acc[i] = Whh[(size_t)r[i] * HID + m];
    }
    for (int k = 0; k < INP; k++) {
        float w = Wfc[k * HID + m];
        #pragma unroll
        for (int i = 0; i < 4; i++) acc[i] += Wih[r[i] * INP + k] * w;
    }
    int chunk = m >> 5, col = m & 31;
    #pragma unroll
    for (int i = 0; i < 4; i++) {
        int np = npb + i;
        int tile = (np >> 7) * 32 + chunk;
        uint32_t bo = sw128((uint32_t)((np & 127) * 128 + col * 4));
        *(float*)((char*)d_Weff + (size_t)tile * TILEB + bo) = to_tf32(acc[i]);
    }
}

// h0 (tf32, tiled+swizzled) and c0 (linear)
__global__ void k_state(const float* __restrict__ hid, const float* __restrict__ cell) {
    int i = blockIdx.x * 256 + threadIdx.x;   // grid 2048
    int b = i >> 10, j = i & 1023;
    int tile = (b >> 7) * 32 + (j >> 5);
    uint32_t bo = sw128((uint32_t)((b & 127) * 128 + (j & 31) * 4));
    *(float*)((char*)d_hbuf[0] + (size_t)tile * TILEB + bo) = to_tf32(hid[i]);
    d_cbuf[i] = cell[i];
}

// u0[b][k] = x0[b][k] - b_fc[k] - h0[b]·W_fc[k]
__global__ void k_u0(const float* __restrict__ xt, const float* __restrict__ hid,
                     const float* __restrict__ Wfc, const float* __restrict__ bfc) {
    __shared__ float hs[HID];
    int b = blockIdx.x, k = threadIdx.x;
    for (int i = k; i < HID; i += 128) hs[i] = hid[b * HID + i];
    __syncthreads();
    float acc = 0.f;
    const float* w = Wfc + k * HID;
    for (int i = 0; i < HID; i++) acc += hs[i] * w[i];
    d_u0[b * INP + k] = xt[b * INP + k] - bfc[k] - acc;
}

// b_eff[n'] = b_ih[r]+b_hh[r]+W_ih[r]·b_fc
__global__ void k_beff(const float* __restrict__ Wih, const float* __restrict__ bih,
                       const float* __restrict__ bhh, const float* __restrict__ bfc) {
    int np = blockIdx.x * 256 + threadIdx.x;
    int r = permrow(np);
    float acc = bih[r] + bhh[r];
    for (int k = 0; k < INP; k++) acc += Wih[r * INP + k] * bfc[k];
    d_beff[np] = acc;
}

// D0[b][n'] = u0[b]·W_ih[r]
__global__ void k_d0(const float* __restrict__ Wih) {
    __shared__ float us[4][INP];
    int tid = threadIdx.x;
    int bq = blockIdx.y;
    int np = blockIdx.x * 128 + tid;
    #pragma unroll
    for (int i = 0; i < 4; i++) us[i][tid] = d_u0[(bq * 4 + i) * INP + tid];
    __syncthreads();
    int r = permrow(np);
    float a0 = 0, a1 = 0, a2 = 0, a3 = 0;
    for (int k = 0; k < INP; k++) {
        float w = Wih[r * INP + k];
        a0 += us[0][k] * w; a1 += us[1][k] * w; a2 += us[2][k] * w; a3 += us[3][k] * w;
    }
    d_D0[(size_t)(bq * 4 + 0) * NG + np] = a0;
    d_D0[(size_t)(bq * 4 + 1) * NG + np] = a1;
    d_D0[(size_t)(bq * 4 + 2) * NG + np] = a2;
    d_D0[(size_t)(bq * 4 + 3) * NG + np] = a3;
}

// ---------------- Step kernel: bulk-copy pipeline + mma.sync tf32 + fused epilogue ----------------
__global__ void __launch_bounds__(256, 1)
k_step(int t, int par, const float* __restrict__ Wfc) {
    extern __shared__ float sm[];                 // STG stages x (A 4096f | B 4096f)
    __shared__ __align__(8) uint64_t mbf[STG];
    __shared__ float s_beff[128];
    __shared__ float s_w127[32];

    const int tid = threadIdx.x, lane = tid & 31, wid = tid >> 5;
    const int wm = wid & 1, wn = wid >> 1;        // 2 x 4 warp grid (64M x 32N)
    const int gid = lane >> 2, tig = lane & 3;
    const int ntile = blockIdx.x, mtile = blockIdx.y;
    const int m0 = mtile * 128, n0 = ntile * 128;

    if (tid < 32) s_w127[tid] = Wfc[127 * HID + ntile * 32 + tid];
    if (tid < 128) s_beff[tid] = d_beff[n0 + tid];
    if (tid == 0) {
        #pragma unroll
        for (int s = 0; s < STG; s++) MBINIT(s2u(&mbf[s]), 1);
        FPROXY();
    }
    __syncthreads();

    const float* Asrc = d_hbuf[par] + (size_t)mtile * 32 * TILEF;
    const float* Bsrc = d_Weff + (size_t)ntile * 32 * TILEF;
    const uint32_t smu = s2u(sm);

    if (tid == 0) {
        #pragma unroll
        for (int s = 0; s < STG; s++) {
            MBEXPECT(s2u(&mbf[s]), 2 * TILEB);
            bulkcp(smu + s * 2 * TILEB, Asrc + s * TILEF, TILEB, s2u(&mbf[s]));
            bulkcp(smu + s * 2 * TILEB + TILEB, Bsrc + s * TILEF, TILEB, s2u(&mbf[s]));
        }
    }

    float acc[4][4][4];
    #pragma unroll
    for (int a = 0; a < 4; a++)
        #pragma unroll
        for (int b = 0; b < 4; b++)
            #pragma unroll
            for (int c = 0; c < 4; c++) acc[a][b][c] = 0.f;

    for (int c = 0; c < NCH; c++) {
        const int s = c & (STG - 1);
        const int ph = (c >> 2) & 1;
        MBWAIT(s2u(&mbf[s]), ph);

        const unsigned* As = (const unsigned*)(sm + s * 2 * TILEF);
        const unsigned* Bs = As + TILEF;
        #pragma unroll
        for (int k8 = 0; k8 < 32; k8 += 8) {
            unsigned a[4][4], b[4][2];
            #pragma unroll
            for (int mf = 0; mf < 4; mf++) {
                int r = wm * 64 + mf * 16 + gid;
                int xr = (r & 7) << 2;
                int c0 = (k8 + tig) ^ xr, c1 = (k8 + tig + 4) ^ xr;
                a[mf][0] = As[r * 32 + c0];
                a[mf][1] = As[(r + 8) * 32 + c0];
                a[mf][2] = As[r * 32 + c1];
                a[mf][3] = As[(r + 8) * 32 + c1];
            }
            #pragma unroll
            for (int nf = 0; nf < 4; nf++) {
                int n = wn * 32 + nf * 8 + gid;
                int xn = (n & 7) << 2;
                b[nf][0] = Bs[n * 32 + ((k8 + tig) ^ xn)];
                b[nf][1] = Bs[n * 32 + ((k8 + tig + 4) ^ xn)];
            }
            #pragma unroll
            for (int mf = 0; mf < 4; mf++)
                #pragma unroll
                for (int nf = 0; nf < 4; nf++) mma8(acc[mf][nf], a[mf], b[nf]);
        }
        __syncthreads();
        if (tid == 0 && c + STG < NCH) {
            MBEXPECT(s2u(&mbf[s]), 2 * TILEB);
            bulkcp(smu + s * 2 * TILEB, Asrc + (c + STG) * TILEF, TILEB, s2u(&mbf[s]));
            bulkcp(smu + s * 2 * TILEB + TILEB, Bsrc + (c + STG) * TILEF, TILEB, s2u(&mbf[s]));
        }
    }
    __syncthreads();

    // dump C tile to smem (stride 132)
    #pragma unroll
    for (int mf = 0; mf < 4; mf++)
        #pragma unroll
        for (int nf = 0; nf < 4; nf++) {
            int row = wm * 64 + mf * 16 + gid;
            int col = wn * 32 + nf * 8 + 2 * tig;
            sm[row * 132 + col]           = acc[mf][nf][0];
            sm[row * 132 + col + 1]       = acc[mf][nf][1];
            sm[(row + 8) * 132 + col]     = acc[mf][nf][2];
            sm[(row + 8) * 132 + col + 1] = acc[mf][nf][3];
        }
    __syncthreads();

    // Fused LSTM epilogue: thread = (batch row bl, half jh of the 32 hidden units)
    {
        const int bl = tid >> 1, jh = tid & 1;
        const int b = m0 + bl;
        float* cb = d_cbuf + (size_t)b * HID + ntile * 32 + jh * 16;
        const float* csm = sm + bl * 132 + jh * 64;
        const float* d0p = d_D0 + (size_t)b * NG + n0 + jh * 64;
        char* hT = (char*)d_hbuf[par ^ 1] + (size_t)(mtile * 32 + ntile) * TILEB;
        float partial = 0.f;

        #pragma unroll
        for (int q = 0; q < 4; q++) {               // 4 groups of 4 units
            float4 cold = *(const float4*)(cb + q * 4);
            float co[4] = {cold.x, cold.y, cold.z, cold.w};
            float hv[4];
            #pragma unroll
            for (int v = 0; v < 4; v++) {
                int g4 = q * 16 + v * 4;
                float gi = csm[g4]     + s_beff[jh * 64 + g4];
                float gf = csm[g4 + 1] + s_beff[jh * 64 + g4 + 1];
                float gg = csm[g4 + 2] + s_beff[jh * 64 + g4 + 2];
                float go = csm[g4 + 3] + s_beff[jh * 64 + g4 + 3];
                if (t == 0) {
                    float4 dd = *(const float4*)(d0p + g4);
                    gi += dd.x; gf += dd.y; gg += dd.z; go += dd.w;
                }
                float cn = sigm(gf) * co[v] + sigm(gi) * tanhf(gg);
                hv[v] = sigm(go) * tanhf(cn);
                co[v] = cn;
                partial += hv[v] * s_w127[jh * 16 + q * 4 + v];
            }
            *(float4*)(cb + q * 4) = make_float4(co[0], co[1], co[2], co[3]);
            uint32_t bo = sw128((uint32_t)(bl * 128 + (jh * 16 + q * 4) * 4));
            *(float4*)(hT + bo) =
                make_float4(to_tf32(hv[0]), to_tf32(hv[1]), to_tf32(hv[2]), to_tf32(hv[3]));
        }
        partial += __shfl_xor_sync(0xffffffffu, partial, 1);
        if (jh == 0) d_part[(size_t)t * (32 * BSZ) + ntile * BSZ + b] = partial;
    }
}

// out[b][t] = b_fc[127] + sum over 32 tiles
__global__ void k_reduce(float* __restrict__ out, const float* __restrict__ bfc) {
    int idx = blockIdx.x * 256 + threadIdx.x;
    if (idx >= BSZ * SEQ) return;
    int b = idx / SEQ, t = idx % SEQ;
    float s = bfc[127];
    #pragma unroll 8
    for (int nt = 0; nt < 32; nt++) s += d_part[(size_t)t * (32 * BSZ) + nt * BSZ + b];
    out[idx] = s;
}

extern "C" void kernel_launch(void* const* d_in, const int* in_sizes, int n_in,
                              void* d_out, int out_size) {
    const float* xt   = (const float*)d_in[0];
    const float* hid  = (const float*)d_in[1];
    const float* cell = (const float*)d_in[2];
    const float* Wih  = (const float*)d_in[3];
    const float* Whh  = (const float*)d_in[4];
    const float* bih  = (const float*)d_in[5];
    const float* bhh  = (const float*)d_in[6];
    const float* Wfc  = (const float*)d_in[7];
    const float* bfc  = (const float*)d_in[8];
    float* out = (float*)d_out;

    cudaFuncSetAttribute(k_step, cudaFuncAttributeMaxDynamicSharedMemorySize, SMEM_BYTES);

    k_weff<<<dim3(4, 1024), 256>>>(Wih, Whh, Wfc);
    k_state<<<2048, 256>>>(hid, cell);
    k_u0<<<512, 128>>>(xt, hid, Wfc, bfc);
    k_beff<<<16, 256>>>(Wih, bih, bhh, bfc);
    k_d0<<<dim3(32, 128), 128>>>(Wih);
    for (int t = 0; t < SEQ; t++)
        k_step<<<dim3(32, 4), 256, SMEM_BYTES>>>(t, t & 1, Wfc);
    k_reduce<<<192, 256>>>(out, bfc);
}

// round 6
// speedup vs baseline: 1.9520x; 1.4665x over previous
#include <cuda_runtime.h>
#include <cuda_fp16.h>
#include <cstdint>

// Sizes
#define BSZ 512
#define HID 1024
#define NG  4096
#define INP 128
#define SEQ 96
#define NCH 16             // K chunks of 64 halfs
#define TILEHF 8192        // halfs per 128x64 tile
#define TILEB 16384        // bytes per tile (128 rows x 128 B)
#define STG 4              // pipeline stages
#define SMEM_BYTES (STG * 2 * TILEB)   // 131072 dynamic

// Scratch (__device__ globals; no cudaMalloc allowed)
__device__ __align__(128) __half d_Weff[(size_t)NG * HID];    // tiled+swizzled [ntile*16+ch][128][64]
__device__ float d_beff[NG];                                  // permuted linear
__device__ float d_D0[(size_t)BSZ * NG];                      // step-0 correction [b][n']
__device__ float d_u0[BSZ * INP];
__device__ __align__(128) __half d_hbuf[2][(size_t)BSZ * HID]; // tiled+swizzled [mtile*16+ch][128][64]
__device__ float d_cbuf[(size_t)BSZ * HID];                   // linear [b][j]
__device__ float d_part[(size_t)SEQ * 32 * BSZ];

__device__ __forceinline__ float sigm(float x) { return 1.0f / (1.0f + __expf(-x)); }
__device__ __forceinline__ int permrow(int np) { return ((np & 3) << 10) | (np >> 2); }
// byte-offset SW128-style swizzle for 128B rows
__device__ __forceinline__ uint32_t sw128(uint32_t o) { return o ^ ((o >> 3) & 0x70); }

__device__ __forceinline__ uint32_t s2u(const void* p) {
    uint32_t a;
    asm("{ .reg .u64 t; cvta.to.shared.u64 t, %1; cvt.u32.u64 %0, t; }" : "=r"(a) : "l"(p));
    return a;
}
__device__ __forceinline__ void bulkcp(uint32_t dst, const void* src, uint32_t bytes, uint32_t mbar) {
    asm volatile(
        "cp.async.bulk.shared::cluster.global.mbarrier::complete_tx::bytes [%0], [%1], %2, [%3];"
        :: "r"(dst), "l"(src), "r"(bytes), "r"(mbar) : "memory");
}
// fp16 mma: D(f32) += A(f16) * B(f16), m16n8k16
__device__ __forceinline__ void mma16(float* c, const unsigned* a, const unsigned* b) {
    asm volatile(
        "mma.sync.aligned.m16n8k16.row.col.f32.f16.f16.f32 "
        "{%0,%1,%2,%3}, {%4,%5,%6,%7}, {%8,%9}, {%0,%1,%2,%3};"
        : "+f"(c[0]), "+f"(c[1]), "+f"(c[2]), "+f"(c[3])
        : "r"(a[0]), "r"(a[1]), "r"(a[2]), "r"(a[3]), "r"(b[0]), "r"(b[1]));
}
#define MBINIT(a, n) \
    asm volatile("mbarrier.init.shared.b64 [%0], %1;" :: "r"(a), "r"(n) : "memory")
#define MBEXPECT(a, n) \
    asm volatile("mbarrier.arrive.expect_tx.shared.b64 _, [%0], %1;" :: "r"(a), "r"(n) : "memory")
#define MBWAIT(a, ph) \
    asm volatile("{\n\t.reg .pred P;\n\tWL_%=: mbarrier.try_wait.parity.acquire.cta.shared::cta.b64 P, [%0], %1, 0x989680;\n\t@P bra.uni WD_%=;\n\tbra.uni WL_%=;\n\tWD_%=:\n\t}" \
                 :: "r"(a), "r"((uint32_t)(ph)) : "memory")
#define FPROXY() asm volatile("fence.proxy.async.shared::cta;" ::: "memory")

// ---------------- Precompute kernels ----------------

// W_eff[n'][m] = W_hh[r][m] + sum_k W_ih[r][k]*W_fc[k][m]; tiled+swizzled fp16 store
__global__ void k_weff(const float* __restrict__ Wih, const float* __restrict__ Whh,
                       const float* __restrict__ Wfc) {
    __shared__ float wih_s[4][INP];
    int m = blockIdx.x * 256 + threadIdx.x;   // grid.x = 4
    int npb = blockIdx.y * 4;                 // grid.y = 1024
    // cache the 4 W_ih rows for this block
    for (int idx = threadIdx.x; idx < 4 * INP; idx += 256)
        wih_s[idx >> 7][idx & 127] = Wih[permrow(npb + (idx >> 7)) * INP + (idx & 127)];
    __syncthreads();
    float acc[4];
    #pragma unroll
    for (int i = 0; i < 4; i++) acc[i] = Whh[(size_t)permrow(npb + i) * HID + m];
    for (int k = 0; k < INP; k++) {
        float w = Wfc[k * HID + m];
        #pragma unroll
        for (int i = 0; i < 4; i++) acc[i] += wih_s[i][k] * w;
    }
    #pragma unroll
    for (int i = 0; i < 4; i++) {
        int np = npb + i;
        int tile = (np >> 7) * 16 + (m >> 6);
        uint32_t bo = sw128((uint32_t)((np & 127) * 128 + (m & 63) * 2));
        *(__half*)((char*)d_Weff + (size_t)tile * TILEB + bo) = __float2half_rn(acc[i]);
    }
}

// h0 (fp16, tiled+swizzled) and c0 (linear)
__global__ void k_state(const float* __restrict__ hid, const float* __restrict__ cell) {
    int i = blockIdx.x * 256 + threadIdx.x;   // grid 2048
    int b = i >> 10, j = i & 1023;
    int tile = (b >> 7) * 16 + (j >> 6);
    uint32_t bo = sw128((uint32_t)((b & 127) * 128 + (j & 63) * 2));
    *(__half*)((char*)d_hbuf[0] + (size_t)tile * TILEB + bo) = __float2half_rn(hid[i]);
    d_cbuf[i] = cell[i];
}

// u0[b][k] = x0[b][k] - b_fc[k] - h0[b]·W_fc[k]
__global__ void k_u0(const float* __restrict__ xt, const float* __restrict__ hid,
                     const float* __restrict__ Wfc, const float* __restrict__ bfc) {
    __shared__ float hs[HID];
    int b = blockIdx.x, k = threadIdx.x;
    for (int i = k; i < HID; i += 128) hs[i] = hid[b * HID + i];
    __syncthreads();
    float acc = 0.f;
    const float* w = Wfc + k * HID;
    for (int i = 0; i < HID; i++) acc += hs[i] * w[i];
    d_u0[b * INP + k] = xt[b * INP + k] - bfc[k] - acc;
}

// b_eff[n'] = b_ih[r]+b_hh[r]+W_ih[r]·b_fc
__global__ void k_beff(const float* __restrict__ Wih, const float* __restrict__ bih,
                       const float* __restrict__ bhh, const float* __restrict__ bfc) {
    int np = blockIdx.x * 256 + threadIdx.x;
    int r = permrow(np);
    float acc = bih[r] + bhh[r];
    for (int k = 0; k < INP; k++) acc += Wih[r * INP + k] * bfc[k];
    d_beff[np] = acc;
}

// D0[b][n'] = u0[b]·W_ih[r]
__global__ void k_d0(const float* __restrict__ Wih) {
    __shared__ float us[4][INP];
    int tid = threadIdx.x;
    int bq = blockIdx.y;
    int np = blockIdx.x * 128 + tid;
    #pragma unroll
    for (int i = 0; i < 4; i++) us[i][tid] = d_u0[(bq * 4 + i) * INP + tid];
    __syncthreads();
    int r = permrow(np);
    float a0 = 0, a1 = 0, a2 = 0, a3 = 0;
    for (int k = 0; k < INP; k++) {
        float w = Wih[r * INP + k];
        a0 += us[0][k] * w; a1 += us[1][k] * w; a2 += us[2][k] * w; a3 += us[3][k] * w;
    }
    d_D0[(size_t)(bq * 4 + 0) * NG + np] = a0;
    d_D0[(size_t)(bq * 4 + 1) * NG + np] = a1;
    d_D0[(size_t)(bq * 4 + 2) * NG + np] = a2;
    d_D0[(size_t)(bq * 4 + 3) * NG + np] = a3;
}

// ---------------- Step kernel: bulk-copy pipeline + fp16 mma + fused epilogue ----------------
__global__ void __launch_bounds__(256, 1)
k_step(int t, int par, const float* __restrict__ Wfc) {
    extern __shared__ float sm[];                 // STG stages x (A tile | B tile), 16KB each
    __shared__ __align__(8) uint64_t mbf[STG];
    __shared__ float s_beff[128];
    __shared__ float s_w127[32];

    const int tid = threadIdx.x, lane = tid & 31, wid = tid >> 5;
    const int wm = wid & 1, wn = wid >> 1;        // 2 x 4 warp grid (64M x 32N)
    const int gid = lane >> 2, tig = lane & 3;
    const int ntile = blockIdx.x, mtile = blockIdx.y;
    const int m0 = mtile * 128, n0 = ntile * 128;

    if (tid < 32) s_w127[tid] = Wfc[127 * HID + ntile * 32 + tid];
    if (tid < 128) s_beff[tid] = d_beff[n0 + tid];
    if (tid == 0) {
        #pragma unroll
        for (int s = 0; s < STG; s++) MBINIT(s2u(&mbf[s]), 1);
        FPROXY();
    }
    __syncthreads();

    const __half* Asrc = d_hbuf[par] + (size_t)mtile * 16 * TILEHF;
    const __half* Bsrc = d_Weff + (size_t)ntile * 16 * TILEHF;
    const uint32_t smu = s2u(sm);

    if (tid == 0) {
        #pragma unroll
        for (int s = 0; s < STG; s++) {
            MBEXPECT(s2u(&mbf[s]), 2 * TILEB);
            bulkcp(smu + s * 2 * TILEB, Asrc + s * TILEHF, TILEB, s2u(&mbf[s]));
            bulkcp(smu + s * 2 * TILEB + TILEB, Bsrc + s * TILEHF, TILEB, s2u(&mbf[s]));
        }
    }

    float acc[4][4][4];
    #pragma unroll
    for (int a = 0; a < 4; a++)
        #pragma unroll
        for (int b = 0; b < 4; b++)
            #pragma unroll
            for (int c = 0; c < 4; c++) acc[a][b][c] = 0.f;

    for (int c = 0; c < NCH; c++) {
        const int s = c & (STG - 1);
        const int ph = (c >> 2) & 1;
        MBWAIT(s2u(&mbf[s]), ph);

        // rows are 32 words of half2 "units"; unit u of row r at word r*32 + (u ^ ((r&7)<<2))
        const unsigned* As = (const unsigned*)(sm + s * 2 * (TILEB / 4));
        const unsigned* Bs = As + TILEB / 4;
        #pragma unroll
        for (int k8 = 0; k8 < 32; k8 += 8) {       // 4 mma k-steps of k16 (8 units each)
            unsigned a[4][4], b[4][2];
            #pragma unroll
            for (int mf = 0; mf < 4; mf++) {
                int r = wm * 64 + mf * 16 + gid;
                int xr = (r & 7) << 2;
                int c0 = (k8 + tig) ^ xr, c1 = (k8 + tig + 4) ^ xr;
                a[mf][0] = As[r * 32 + c0];
                a[mf][1] = As[(r + 8) * 32 + c0];
                a[mf][2] = As[r * 32 + c1];
                a[mf][3] = As[(r + 8) * 32 + c1];
            }
            #pragma unroll
            for (int nf = 0; nf < 4; nf++) {
                int n = wn * 32 + nf * 8 + gid;
                int xn = (n & 7) << 2;
                b[nf][0] = Bs[n * 32 + ((k8 + tig) ^ xn)];
                b[nf][1] = Bs[n * 32 + ((k8 + tig + 4) ^ xn)];
            }
            #pragma unroll
            for (int mf = 0; mf < 4; mf++)
                #pragma unroll
                for (int nf = 0; nf < 4; nf++) mma16(acc[mf][nf], a[mf], b[nf]);
        }
        __syncthreads();
        if (tid == 0 && c + STG < NCH) {
            MBEXPECT(s2u(&mbf[s]), 2 * TILEB);
            bulkcp(smu + s * 2 * TILEB, Asrc + (c + STG) * TILEHF, TILEB, s2u(&mbf[s]));
            bulkcp(smu + s * 2 * TILEB + TILEB, Bsrc + (c + STG) * TILEHF, TILEB, s2u(&mbf[s]));
        }
    }
    __syncthreads();

    // dump C tile to smem (stride 132)
    #pragma unroll
    for (int mf = 0; mf < 4; mf++)
        #pragma unroll
        for (int nf = 0; nf < 4; nf++) {
            int row = wm * 64 + mf * 16 + gid;
            int col = wn * 32 + nf * 8 + 2 * tig;
            sm[row * 132 + col]           = acc[mf][nf][0];
            sm[row * 132 + col + 1]       = acc[mf][nf][1];
            sm[(row + 8) * 132 + col]     = acc[mf][nf][2];
            sm[(row + 8) * 132 + col + 1] = acc[mf][nf][3];
        }
    __syncthreads();

    // Fused LSTM epilogue: thread = (batch row bl, half jh of the 32 hidden units)
    {
        const int bl = tid >> 1, jh = tid & 1;
        const int b = m0 + bl;
        float* cb = d_cbuf + (size_t)b * HID + ntile * 32 + jh * 16;
        const float* csm = sm + bl * 132 + jh * 64;
        const float* d0p = d_D0 + (size_t)b * NG + n0 + jh * 64;
        // h for next step: hidden unit j = ntile*32 + jl lives in chunk j/64, half-col j%64
        char* hT = (char*)d_hbuf[par ^ 1] + (size_t)(mtile * 16 + (ntile >> 1)) * TILEB;
        const int colbase = (ntile & 1) * 64 + jh * 32;   // byte offset of jl=jh*16 within row
        float partial = 0.f;

        #pragma unroll
        for (int q = 0; q < 4; q++) {               // 4 groups of 4 units
            float4 cold = *(const float4*)(cb + q * 4);
            float co[4] = {cold.x, cold.y, cold.z, cold.w};
            float hv[4];
            #pragma unroll
            for (int v = 0; v < 4; v++) {
                int g4 = q * 16 + v * 4;
                float gi = csm[g4]     + s_beff[jh * 64 + g4];
                float gf = csm[g4 + 1] + s_beff[jh * 64 + g4 + 1];
                float gg = csm[g4 + 2] + s_beff[jh * 64 + g4 + 2];
                float go = csm[g4 + 3] + s_beff[jh * 64 + g4 + 3];
                if (t == 0) {
                    float4 dd = *(const float4*)(d0p + g4);
                    gi += dd.x; gf += dd.y; gg += dd.z; go += dd.w;
                }
                float cn = sigm(gf) * co[v] + sigm(gi) * tanhf(gg);
                hv[v] = sigm(go) * tanhf(cn);
                co[v] = cn;
                partial += hv[v] * s_w127[jh * 16 + q * 4 + v];
            }
            *(float4*)(cb + q * 4) = make_float4(co[0], co[1], co[2], co[3]);
            uint32_t bo = (uint32_t)(bl * 128 + colbase + q * 8);
            __half2 p01 = __floats2half2_rn(hv[0], hv[1]);
            __half2 p23 = __floats2half2_rn(hv[2], hv[3]);
            uint32_t sw = sw128(bo);
            *(__half2*)(hT + sw)     = p01;
            *(__half2*)(hT + sw + 4) = p23;
        }
        partial += __shfl_xor_sync(0xffffffffu, partial, 1);
        if (jh == 0) d_part[(size_t)t * (32 * BSZ) + ntile * BSZ + b] = partial;
    }
}

// out[b][t] = b_fc[127] + sum over 32 tiles
__global__ void k_reduce(float* __restrict__ out, const float* __restrict__ bfc) {
    int idx = blockIdx.x * 256 + threadIdx.x;
    if (idx >= BSZ * SEQ) return;
    int b = idx / SEQ, t = idx % SEQ;
    float s = bfc[127];
    #pragma unroll 8
    for (int nt = 0; nt < 32; nt++) s += d_part[(size_t)t * (32 * BSZ) + nt * BSZ + b];
    out[idx] = s;
}

extern "C" void kernel_launch(void* const* d_in, const int* in_sizes, int n_in,
                              void* d_out, int out_size) {
    const float* xt   = (const float*)d_in[0];
    const float* hid  = (const float*)d_in[1];
    const float* cell = (const float*)d_in[2];
    const float* Wih  = (const float*)d_in[3];
    const float* Whh  = (const float*)d_in[4];
    const float* bih  = (const float*)d_in[5];
    const float* bhh  = (const float*)d_in[6];
    const float* Wfc  = (const float*)d_in[7];
    const float* bfc  = (const float*)d_in[8];
    float* out = (float*)d_out;

    cudaFuncSetAttribute(k_step, cudaFuncAttributeMaxDynamicSharedMemorySize, SMEM_BYTES);

    k_weff<<<dim3(4, 1024), 256>>>(Wih, Whh, Wfc);
    k_state<<<2048, 256>>>(hid, cell);
    k_u0<<<512, 128>>>(xt, hid, Wfc, bfc);
    k_beff<<<16, 256>>>(Wih, bih, bhh, bfc);
    k_d0<<<dim3(32, 128), 128>>>(Wih);
    for (int t = 0; t < SEQ; t++)
        k_step<<<dim3(32, 4), 256, SMEM_BYTES>>>(t, t & 1, Wfc);
    k_reduce<<<192, 256>>>(out, bfc);
}